// round 10
// baseline (speedup 1.0000x reference)
#include <cuda_runtime.h>

// SNN forward scan: rows = B*N = 65536 independent length-512 recurrences.
// R10: DRAM-page-locality, 2x R9 contiguity. One warp per block, 32 rows.
// CHUNK=256 timesteps -> every row-stage moves a contiguous 1 KB run.
// Double-buffered cp.async (dynamic smem, 66.5 KB -> 3 blocks/SM),
// issue-then-wait so a full 32 KB group is in flight during each wait.
// Refractory window as multiplicative mask: ic = x*(1-s[t-1])*(1-s[t-2]).

#define T_STEPS 512
#define CHUNK   256
#define ROWS    32                // threads per block == rows per block
#define NCHUNK  (T_STEPS / CHUNK) // 2
#define STRIDE  260               // padded smem row stride (floats); 260%32=4 -> conflict-free
#define NBUF    2
#define LDI     64                // coop iterations per stage: ROWS*CHUNK/(32*4)

__device__ __forceinline__ void cp_async16(float* smem_dst, const float* gmem_src) {
    unsigned saddr = (unsigned)__cvta_generic_to_shared(smem_dst);
    asm volatile("cp.async.cg.shared.global [%0], [%1], 16;\n"
                 :: "r"(saddr), "l"(gmem_src));
}

extern __shared__ float tile_dyn[];   // [NBUF][ROWS * STRIDE]

__global__ __launch_bounds__(ROWS) void snn_fwd_kernel(
    const float* __restrict__ x,
    const float* __restrict__ beta,
    const float* __restrict__ p,
    const float* __restrict__ b,
    float* __restrict__ out,
    int N)
{
    float* tile0 = tile_dyn;
    float* tile1 = tile_dyn + ROWS * STRIDE;

    const int tid = threadIdx.x;
    const size_t row_base = (size_t)blockIdx.x * ROWS;
    const int n = (int)((row_base + tid) % (size_t)N);

    // clamped effective per-neuron params
    const float beta_c = fminf(fmaxf(beta[n], 0.001f), 0.999f);
    const float p_c    = fminf(fabsf(p[n]), 0.999f);
    const float b_c    = fminf(fmaxf(fabsf(b[n]), 0.001f), 1.0f);

    // recurrence state
    float mem = 0.0f, a = 0.0f, vth = 1.0f;
    float m1 = 1.0f, m2 = 1.0f;   // 1 - s(t-1), 1 - s(t-2)

    // cooperative addressing: g = k*32 + tid; r = g>>6 (row), c4 = g&63
    // (16B slot within the 1KB row-chunk). Iterations 2r, 2r+1 cover row r's
    // full 1 KB contiguously -> long single-page DRAM bursts.

    // preload chunk 0
    #pragma unroll 16
    for (int k = 0; k < LDI; ++k) {
        const int g = k * ROWS + tid;
        const int r = g >> 6, c4 = g & 63;
        cp_async16(tile0 + r * STRIDE + c4 * 4,
                   x + (row_base + r) * T_STEPS + c4 * 4);
    }
    asm volatile("cp.async.commit_group;\n");

    for (int c = 0; c < NCHUNK; ++c) {
        float* buf = (c & 1) ? tile1 : tile0;

        // issue next stage first (keeps a 32 KB group in flight during wait)
        if (c + 1 < NCHUNK) {
            float* nbuf = (c & 1) ? tile0 : tile1;
            #pragma unroll 16
            for (int k = 0; k < LDI; ++k) {
                const int g = k * ROWS + tid;
                const int r = g >> 6, c4 = g & 63;
                cp_async16(nbuf + r * STRIDE + c4 * 4,
                           x + (row_base + r) * T_STEPS + (c + 1) * CHUNK + c4 * 4);
            }
            asm volatile("cp.async.commit_group;\n");
            asm volatile("cp.async.wait_group 1;\n");   // stage c arrived
        } else {
            asm volatile("cp.async.wait_group 0;\n");
        }
        __syncwarp();

        // compute: each thread owns one smem row; overwrite x with spikes
        float* rowp = buf + tid * STRIDE;
        #pragma unroll 8
        for (int i = 0; i < CHUNK / 4; ++i) {
            float4 xv = *reinterpret_cast<float4*>(rowp + i * 4);
            float4 ov;
            #pragma unroll
            for (int k = 0; k < 4; ++k) {
                const float xt = (k == 0) ? xv.x : (k == 1) ? xv.y
                               : (k == 2) ? xv.z : xv.w;
                const float ic = xt * (m1 * m2);          // refractory mask
                const float nm = fmaf(mem, beta_c, ic);   // leaky integrate
                const float ns = (nm > vth) ? 0.0f : 1.0f;
                const float s  = 1.0f - ns;
                mem = nm * ns;                            // reset-to-zero
                a   = fmaf(p_c, a, s);                    // adaptation
                vth = fmaf(b_c, a, 1.0f);
                m2 = m1; m1 = ns;
                if (k == 0) ov.x = s; else if (k == 1) ov.y = s;
                else if (k == 2) ov.z = s; else ov.w = s;
            }
            *reinterpret_cast<float4*>(rowp + i * 4) = ov;
        }
        __syncwarp();   // spikes visible warp-wide for cooperative store

        // cooperative store: contiguous 1 KB run per row
        #pragma unroll 16
        for (int k = 0; k < LDI; ++k) {
            const int g = k * ROWS + tid;
            const int r = g >> 6, c4 = g & 63;
            const float4 v = *reinterpret_cast<const float4*>(
                buf + r * STRIDE + c4 * 4);
            __stcs(reinterpret_cast<float4*>(
                out + (row_base + r) * T_STEPS + c * CHUNK + c4 * 4), v);
        }
        // buffer reuse: next stage's prefetch into this buffer is issued at
        // the top of iteration c+1, program-ordered after this store loop
        // (same thread covers the same smem addresses in both loops).
    }
}

extern "C" void kernel_launch(void* const* d_in, const int* in_sizes, int n_in,
                              void* d_out, int out_size)
{
    const float* x    = (const float*)d_in[0];
    const float* beta = (const float*)d_in[1];
    const float* p    = (const float*)d_in[2];
    const float* b    = (const float*)d_in[3];
    float* out        = (float*)d_out;

    const int N    = in_sizes[1];               // 1024
    const int rows = in_sizes[0] / T_STEPS;     // B*N = 65536

    const int smem_bytes = NBUF * ROWS * STRIDE * sizeof(float);  // 66560
    static int configured = 0;
    if (!configured) {
        cudaFuncSetAttribute(snn_fwd_kernel,
                             cudaFuncAttributeMaxDynamicSharedMemorySize,
                             smem_bytes);
        configured = 1;
    }

    const int blocks = rows / ROWS;             // 2048
    snn_fwd_kernel<<<blocks, ROWS, smem_bytes>>>(x, beta, p, b, out, N);
}

// round 11
// speedup vs baseline: 1.1452x; 1.1452x over previous
#include <cuda_runtime.h>

// SNN forward scan: rows = B*N = 65536 independent length-512 recurrences.
// R11: persistent-block seamless pipeline at the R9 shape. One warp per
// block, 32 rows per group, CHUNK=128 (each coop iteration moves one row's
// contiguous 512 B run). Each block processes 2 groups (g, g+NB) as one
// continuous 8-stage double-buffered cp.async stream -- no pipeline
// fill/drain at group boundaries. Spike chain uses direct FSELs
// (mem = sp?0:nm) and reassociated refractory mask ic=(xt*m2)*m1.

#define T_STEPS 512
#define CHUNK   128
#define ROWS    32                 // threads per block == rows per group
#define NCHUNK  (T_STEPS / CHUNK)  // 4 stages per group
#define GPB     2                  // groups per block
#define NSTAGE  (NCHUNK * GPB)     // 8 stages per block
#define STRIDE  132                // padded smem row stride (floats)
#define LDI     32                 // coop iterations per stage (one row each)

__device__ __forceinline__ void cp_async16(float* smem_dst, const float* gmem_src) {
    unsigned saddr = (unsigned)__cvta_generic_to_shared(smem_dst);
    asm volatile("cp.async.cg.shared.global [%0], [%1], 16;\n"
                 :: "r"(saddr), "l"(gmem_src));
}

__global__ __launch_bounds__(ROWS) void snn_fwd_kernel(
    const float* __restrict__ x,
    const float* __restrict__ beta,
    const float* __restrict__ p,
    const float* __restrict__ b,
    float* __restrict__ out,
    int N, int NB)
{
    __shared__ float tile[2][ROWS * STRIDE];

    const int tid = threadIdx.x;
    const int bid = blockIdx.x;

    // stage t (0..7): group gi = t>>2 (block handles groups bid, bid+NB),
    // chunk = t&3, buffer = t&1. Prefetch iteration k loads row k's 512 B run.
    auto stage_base = [&](int t) -> const float* {
        const size_t rowb = (size_t)(bid + (t >> 2) * NB) * ROWS;
        return x + rowb * T_STEPS + (size_t)(t & 3) * CHUNK;
    };

    // preload stages 0 and 1
    #pragma unroll
    for (int t = 0; t < 2; ++t) {
        const float* base = stage_base(t);
        #pragma unroll
        for (int k = 0; k < LDI; ++k)
            cp_async16(&tile[t][k * STRIDE + tid * 4], base + k * T_STEPS + tid * 4);
        asm volatile("cp.async.commit_group;\n");
    }

    for (int gi = 0; gi < GPB; ++gi) {
        const size_t row_base = (size_t)(bid + gi * NB) * ROWS;
        const int n = (int)((row_base + tid) % (size_t)N);

        // clamped effective per-neuron params (per group)
        const float beta_c = fminf(fmaxf(beta[n], 0.001f), 0.999f);
        const float p_c    = fminf(fabsf(p[n]), 0.999f);
        const float b_c    = fminf(fmaxf(fabsf(b[n]), 0.001f), 1.0f);

        // recurrence state (per group)
        float mem = 0.0f, a = 0.0f, vth = 1.0f;
        float m1 = 1.0f, m2 = 1.0f;   // 1 - s(t-1), 1 - s(t-2)

        for (int c = 0; c < NCHUNK; ++c) {
            const int s = gi * NCHUNK + c;
            float* buf = tile[s & 1];

            // wait for stage s (stage s+1 may remain in flight)
            if (s + 1 < NSTAGE) asm volatile("cp.async.wait_group 1;\n");
            else                asm volatile("cp.async.wait_group 0;\n");
            __syncwarp();

            // compute: each thread owns one smem row; overwrite x with spikes
            float* rowp = buf + tid * STRIDE;
            #pragma unroll 8
            for (int i = 0; i < CHUNK / 4; ++i) {
                float4 xv = *reinterpret_cast<float4*>(rowp + i * 4);
                float4 ov;
                #pragma unroll
                for (int k = 0; k < 4; ++k) {
                    const float xt = (k == 0) ? xv.x : (k == 1) ? xv.y
                                   : (k == 2) ? xv.z : xv.w;
                    const float ic = (xt * m2) * m1;          // refractory mask
                    const float nm = fmaf(mem, beta_c, ic);   // leaky integrate
                    const bool  sp = nm > vth;
                    const float sv = sp ? 1.0f : 0.0f;
                    const float nmk = sp ? 0.0f : nm;         // reset-to-zero
                    const float nsk = sp ? 0.0f : 1.0f;
                    mem = nmk;
                    a   = fmaf(p_c, a, sv);                   // adaptation
                    vth = fmaf(b_c, a, 1.0f);
                    m2 = m1; m1 = nsk;
                    if (k == 0) ov.x = sv; else if (k == 1) ov.y = sv;
                    else if (k == 2) ov.z = sv; else ov.w = sv;
                }
                *reinterpret_cast<float4*>(rowp + i * 4) = ov;
            }
            __syncwarp();

            // cooperative store: one contiguous 512 B run per iteration
            {
                float* obase = out + row_base * T_STEPS + (size_t)c * CHUNK;
                #pragma unroll
                for (int k = 0; k < LDI; ++k) {
                    const float4 v = *reinterpret_cast<const float4*>(
                        buf + k * STRIDE + tid * 4);
                    __stcs(reinterpret_cast<float4*>(
                        obase + k * T_STEPS + tid * 4), v);
                }
            }

            // prefetch stage s+2 into this buffer (crosses group boundary)
            if (s + 2 < NSTAGE) {
                const float* base = stage_base(s + 2);
                #pragma unroll
                for (int k = 0; k < LDI; ++k)
                    cp_async16(buf + k * STRIDE + tid * 4,
                               base + k * T_STEPS + tid * 4);
                asm volatile("cp.async.commit_group;\n");
            }
        }
    }
}

extern "C" void kernel_launch(void* const* d_in, const int* in_sizes, int n_in,
                              void* d_out, int out_size)
{
    const float* x    = (const float*)d_in[0];
    const float* beta = (const float*)d_in[1];
    const float* p    = (const float*)d_in[2];
    const float* b    = (const float*)d_in[3];
    float* out        = (float*)d_out;

    const int N      = in_sizes[1];                 // 1024
    const int rows   = in_sizes[0] / T_STEPS;       // B*N = 65536
    const int groups = rows / ROWS;                 // 2048
    const int NB     = groups / GPB;                // 1024 blocks

    snn_fwd_kernel<<<NB, ROWS>>>(x, beta, p, b, out, N, NB);
}